// round 1
// baseline (speedup 1.0000x reference)
#include <cuda_runtime.h>

// Complex-valued scaled-dot-product attention, B=8 H=8 S=1024 D=64, fp32.
//   attn = (q/8) . k   (complex, no conjugate)
//   f    = (|attn| - rowmin|attn|) / ((rowmax-rowmin) * |attn|)
//   out  = (attn * f) @ v   (complex), output stacked [real, imag]
//
// 3 kernels: QK GEMM (+ mag^2 min/max partials) -> row reduce -> normalize+AV GEMM.
// All heavy math uses packed fma.rn.f32x2 (2x fp32 FMA throughput on sm_103a).

#define BHN 64
#define SEQ 1024
#define NKT 16

typedef unsigned long long u64;

// Scratch (device globals: no allocation allowed in kernel_launch).
__device__ float g_ar[(size_t)BHN * SEQ * SEQ];     // 256 MB
__device__ float g_ai[(size_t)BHN * SEQ * SEQ];     // 256 MB
__device__ float g_pmin[BHN * SEQ * NKT];
__device__ float g_pmax[BHN * SEQ * NKT];
__device__ float g_mn[BHN * SEQ];
__device__ float g_inv[BHN * SEQ];

__device__ __forceinline__ u64 pk(float lo, float hi) {
    u64 r; asm("mov.b64 %0, {%1,%2};" : "=l"(r) : "f"(lo), "f"(hi)); return r;
}
__device__ __forceinline__ float2 upk(u64 v) {
    float2 f; asm("mov.b64 {%0,%1}, %2;" : "=f"(f.x), "=f"(f.y) : "l"(v)); return f;
}
__device__ __forceinline__ void fma2(u64& d, u64 a, u64 b) {
    asm("fma.rn.f32x2 %0, %1, %2, %0;" : "+l"(d) : "l"(a), "l"(b));
}

// ---------------------------------------------------------------------------
// K1: attn = (q/8) . k  (complex QK^T), 64x64 tile per block, D=64 reduction.
// Writes attn to gmem scratch + per-(row, ktile) mag^2 min/max partials.
// SMEM: Qa[d][q]=(qr,qr), Qb[d][q]=(-qi,qi), Ka[d][k]=(kr,ki), row stride 65.
// ---------------------------------------------------------------------------
__global__ __launch_bounds__(256, 2) void qk_kernel(
    const float* __restrict__ qr, const float* __restrict__ qi,
    const float* __restrict__ kr, const float* __restrict__ ki)
{
    extern __shared__ float2 smem1[];
    float2* Qa = smem1;
    float2* Qb = Qa + 64 * 65;
    float2* Ka = Qb + 64 * 65;

    const int kt = blockIdx.x, qt = blockIdx.y, bh = blockIdx.z;
    const int tid = threadIdx.x;
    const int qbase = ((bh << 10) + (qt << 6)) << 6;
    const int kbase = ((bh << 10) + (kt << 6)) << 6;

    // Fill: lane = d (coalesced LDG; STS 2-way conflict max with 65-stride)
    #pragma unroll
    for (int it = 0; it < 16; ++it) {
        int idx = tid + (it << 8);
        int d = idx & 63, row = idx >> 6;
        float a = qr[qbase + (row << 6) + d] * 0.125f;
        float b = qi[qbase + (row << 6) + d] * 0.125f;
        Qa[d * 65 + row] = make_float2(a, a);
        Qb[d * 65 + row] = make_float2(-b, b);
        float c = kr[kbase + (row << 6) + d];
        float e = ki[kbase + (row << 6) + d];
        Ka[d * 65 + row] = make_float2(c, e);
    }
    __syncthreads();

    const int ty = tid >> 4, tx = tid & 15;
    u64 acc[4][4];
    #pragma unroll
    for (int i = 0; i < 4; i++)
        #pragma unroll
        for (int j = 0; j < 4; j++) acc[i][j] = 0ULL;

    // q rows: qt*64 + 4*ty + i (blocked); k cols: kt*64 + tx + 16*j (strided,
    // conflict-free LDS). (cr,ci) += (qr,qr)*(kr,ki) + (-qi,qi)*(ki,kr).
    #pragma unroll 4
    for (int d = 0; d < 64; ++d) {
        const float2* qaR = Qa + d * 65 + (ty << 2);
        const float2* qbR = Qb + d * 65 + (ty << 2);
        const float2* kaR = Ka + d * 65 + tx;
        u64 qa[4], qb[4], ka[4], kb[4];
        #pragma unroll
        for (int i = 0; i < 4; i++) {
            qa[i] = *reinterpret_cast<const u64*>(qaR + i);
            qb[i] = *reinterpret_cast<const u64*>(qbR + i);
        }
        #pragma unroll
        for (int j = 0; j < 4; j++) {
            float2 k2 = kaR[j << 4];
            ka[j] = pk(k2.x, k2.y);
            kb[j] = pk(k2.y, k2.x);
        }
        #pragma unroll
        for (int i = 0; i < 4; i++)
            #pragma unroll
            for (int j = 0; j < 4; j++) {
                fma2(acc[i][j], qa[i], ka[j]);
                fma2(acc[i][j], qb[i], kb[j]);
            }
    }

    // Epilogue: store attn, fold mag^2 min/max, warp-shuffle reduce over tx.
    float mn_[4], mx_[4];
    #pragma unroll
    for (int i = 0; i < 4; i++) {
        int qrow = (qt << 6) + (ty << 2) + i;
        int base = ((bh << 10) + qrow) << 10;
        float mnv = 3.4e38f, mxv = 0.0f;
        #pragma unroll
        for (int j = 0; j < 4; j++) {
            int kc = (kt << 6) + tx + (j << 4);
            float2 c = upk(acc[i][j]);
            g_ar[base + kc] = c.x;
            g_ai[base + kc] = c.y;
            float m2 = c.x * c.x + c.y * c.y;
            mnv = fminf(mnv, m2);
            mxv = fmaxf(mxv, m2);
        }
        mn_[i] = mnv; mx_[i] = mxv;
    }
    #pragma unroll
    for (int off = 8; off >= 1; off >>= 1) {
        #pragma unroll
        for (int i = 0; i < 4; i++) {
            mn_[i] = fminf(mn_[i], __shfl_xor_sync(0xffffffffu, mn_[i], off));
            mx_[i] = fmaxf(mx_[i], __shfl_xor_sync(0xffffffffu, mx_[i], off));
        }
    }
    if (tx == 0) {
        #pragma unroll
        for (int i = 0; i < 4; i++) {
            int qrow = (qt << 6) + (ty << 2) + i;
            g_pmin[((bh << 10) + qrow) * NKT + kt] = mn_[i];
            g_pmax[((bh << 10) + qrow) * NKT + kt] = mx_[i];
        }
    }
}

// ---------------------------------------------------------------------------
// K2: reduce 16 partials per row -> mn = sqrt(min m2), inv = 1/(mx - mn).
// ---------------------------------------------------------------------------
__global__ void minmax_kernel()
{
    int r = blockIdx.x * 256 + threadIdx.x;   // 65536 rows exactly
    float mn2 = g_pmin[r * NKT], mx2 = g_pmax[r * NKT];
    #pragma unroll
    for (int t = 1; t < NKT; t++) {
        mn2 = fminf(mn2, g_pmin[r * NKT + t]);
        mx2 = fmaxf(mx2, g_pmax[r * NKT + t]);
    }
    float mnv = sqrtf(mn2), mxv = sqrtf(mx2);
    g_mn[r] = mnv;
    g_inv[r] = 1.0f / (mxv - mnv);
}

// ---------------------------------------------------------------------------
// K3: out = normalize(attn) @ v (complex). 64q x 64d tile per block,
// streaming k in chunks of 64. Normalization fused into the smem fill:
//   rm = rsqrt(m2); mag = m2*rm; f = (mag - mn)*inv*rm.
// (or,oi) += (ar,ar)*(vr,vi) + (-ai,ai)*(vi,vr).
// ---------------------------------------------------------------------------
__global__ __launch_bounds__(256, 2) void av_kernel(
    const float* __restrict__ vr, const float* __restrict__ vi,
    float* __restrict__ out)
{
    extern __shared__ float2 smem3[];
    float2* Aa = smem3;
    float2* Ab = Aa + 64 * 65;
    float2* Va = Ab + 64 * 65;
    __shared__ float smn[64], sinv[64];

    const int qt = blockIdx.x, bh = blockIdx.y;
    const int tid = threadIdx.x;
    if (tid < 64) {
        int r = (bh << 10) + (qt << 6) + tid;
        smn[tid] = g_mn[r];
        sinv[tid] = g_inv[r];
    }
    __syncthreads();

    const int ty = tid >> 4, tx = tid & 15;
    u64 acc[4][4];
    #pragma unroll
    for (int i = 0; i < 4; i++)
        #pragma unroll
        for (int j = 0; j < 4; j++) acc[i][j] = 0ULL;

    const int abase = ((bh << 10) + (qt << 6)) << 10;

    for (int c = 0; c < 16; ++c) {
        // Fill attn chunk (normalized) and V chunk.
        #pragma unroll
        for (int it = 0; it < 16; ++it) {
            int idx = tid + (it << 8);
            int kf = idx & 63, q = idx >> 6;          // attn: lane = k (coalesced)
            int ao = abase + (q << 10) + (c << 6) + kf;
            float ar = g_ar[ao], ai = g_ai[ao];
            float m2 = ar * ar + ai * ai;
            float rm = rsqrtf(m2);
            float f = (m2 * rm - smn[q]) * sinv[q] * rm;
            float arn = ar * f, ain = ai * f;
            Aa[kf * 65 + q] = make_float2(arn, arn);
            Ab[kf * 65 + q] = make_float2(-ain, ain);
            int d = idx & 63, krow = idx >> 6;        // V: lane = d (coalesced)
            int vo = (((bh << 10) + (c << 6) + krow) << 6) + d;
            Va[krow * 65 + d] = make_float2(vr[vo], vi[vo]);
        }
        __syncthreads();

        #pragma unroll 4
        for (int kk = 0; kk < 64; ++kk) {
            const float2* aaR = Aa + kk * 65 + (ty << 2);
            const float2* abR = Ab + kk * 65 + (ty << 2);
            const float2* vaR = Va + kk * 65 + tx;
            u64 aa[4], ab[4], va[4], vb[4];
            #pragma unroll
            for (int i = 0; i < 4; i++) {
                aa[i] = *reinterpret_cast<const u64*>(aaR + i);
                ab[i] = *reinterpret_cast<const u64*>(abR + i);
            }
            #pragma unroll
            for (int j = 0; j < 4; j++) {
                float2 v2 = vaR[j << 4];
                va[j] = pk(v2.x, v2.y);
                vb[j] = pk(v2.y, v2.x);
            }
            #pragma unroll
            for (int i = 0; i < 4; i++)
                #pragma unroll
                for (int j = 0; j < 4; j++) {
                    fma2(acc[i][j], aa[i], va[j]);
                    fma2(acc[i][j], ab[i], vb[j]);
                }
        }
        __syncthreads();
    }

    // Output: [2][BH][S][D], real then imag (imag offset = 64*1024*64).
    #pragma unroll
    for (int i = 0; i < 4; i++) {
        int qrow = (qt << 6) + (ty << 2) + i;
        int ob = ((bh << 10) + qrow) << 6;
        #pragma unroll
        for (int j = 0; j < 4; j++) {
            int d = tx + (j << 4);
            float2 cc = upk(acc[i][j]);
            out[ob + d] = cc.x;
            out[ob + d + 4194304] = cc.y;
        }
    }
}

extern "C" void kernel_launch(void* const* d_in, const int* in_sizes, int n_in,
                              void* d_out, int out_size)
{
    (void)in_sizes; (void)n_in; (void)out_size;
    const float* qr = (const float*)d_in[0];
    const float* qi = (const float*)d_in[1];
    const float* kr = (const float*)d_in[2];
    const float* ki = (const float*)d_in[3];
    const float* vr = (const float*)d_in[4];
    const float* vi = (const float*)d_in[5];
    float* out = (float*)d_out;

    const int smem = 3 * 64 * 65 * (int)sizeof(float2);  // 99840 bytes
    cudaFuncSetAttribute(qk_kernel, cudaFuncAttributeMaxDynamicSharedMemorySize, smem);
    cudaFuncSetAttribute(av_kernel, cudaFuncAttributeMaxDynamicSharedMemorySize, smem);

    qk_kernel<<<dim3(16, 16, 64), 256, smem>>>(qr, qi, kr, ki);
    minmax_kernel<<<256, 256>>>();
    av_kernel<<<dim3(16, 64), 256, smem>>>(vr, vi, out);
}

// round 2
// speedup vs baseline: 1.0007x; 1.0007x over previous
#include <cuda_runtime.h>

// Complex-valued scaled-dot-product attention, B=8 H=8 S=1024 D=64, fp32.
// R2: swap-free packed-f32x2 MACs (column-pair packing), 3 CTAs/SM.

#define BHN 64
#define SEQ 1024
#define NKT 16
#define SQ 66   // stride (float2) of broadcast arrays [32][64q]
#define SK 34   // stride (float2) of vector arrays   [32][32pair]

typedef unsigned long long u64;

__device__ float g_ar[(size_t)BHN * SEQ * SEQ];     // 256 MB
__device__ float g_ai[(size_t)BHN * SEQ * SEQ];     // 256 MB
__device__ float g_pmin[BHN * SEQ * NKT];
__device__ float g_pmax[BHN * SEQ * NKT];
__device__ float g_mn[BHN * SEQ];
__device__ float g_inv[BHN * SEQ];

__device__ __forceinline__ u64 pk(float lo, float hi) {
    u64 r; asm("mov.b64 %0, {%1,%2};" : "=l"(r) : "f"(lo), "f"(hi)); return r;
}
__device__ __forceinline__ float2 upk(u64 v) {
    float2 f; asm("mov.b64 {%0,%1}, %2;" : "=f"(f.x), "=f"(f.y) : "l"(v)); return f;
}
__device__ __forceinline__ void fma2(u64& d, u64 a, u64 b) {
    asm("fma.rn.f32x2 %0, %1, %2, %0;" : "+l"(d) : "l"(a), "l"(b));
}
__device__ __forceinline__ u64 mul2(u64 a, u64 b) {
    u64 d; asm("mul.rn.f32x2 %0, %1, %2;" : "=l"(d) : "l"(a), "l"(b)); return d;
}

union F4U { float4 f; u64 u[2]; };

// ---------------------------------------------------------------------------
// K1: attn = (q/8).k complex QK^T. 64q x 64k tile, d-reduction in 2 stages
// of 32 (halves smem -> 3 CTAs/SM). Thread tile 4q x 4k, k packed as
// (k, k+32) column pairs; acc lanes = (cr[k],cr[k+32]) / (ci...).
// ---------------------------------------------------------------------------
__global__ __launch_bounds__(256, 3) void qk_kernel(
    const float* __restrict__ qr, const float* __restrict__ qi,
    const float* __restrict__ kr, const float* __restrict__ ki)
{
    extern __shared__ float2 sm[];
    float2* Qa  = sm;                 // [32][SQ] (qr,qr)/8
    float2* Qc  = Qa  + 32 * SQ;      // [32][SQ] (qi,qi)/8
    float2* Kr2 = Qc  + 32 * SQ;      // [32][SK] (kr[p],kr[p+32])
    float2* Ki2 = Kr2 + 32 * SK;      // [32][SK] (ki[p],ki[p+32])

    const int kt = blockIdx.x, qt = blockIdx.y, bh = blockIdx.z;
    const int tid = threadIdx.x;
    const int qbase = ((bh << 10) + (qt << 6)) << 6;
    const int kbase = ((bh << 10) + (kt << 6)) << 6;
    const int ty = tid >> 4, tx = tid & 15;
    const u64 NEG1 = pk(-1.0f, -1.0f);

    u64 accr[4][2], acci[4][2];
    #pragma unroll
    for (int i = 0; i < 4; i++) { accr[i][0]=0; accr[i][1]=0; acci[i][0]=0; acci[i][1]=0; }

    for (int h = 0; h < 2; ++h) {
        const int hd = h << 5;
        // Q fill: 32d x 64q, lane = d (coalesced LDG)
        #pragma unroll
        for (int it = 0; it < 8; ++it) {
            int idx = tid + (it << 8);
            int d = idx & 31, q = idx >> 5, gd = hd + d;
            float a = qr[qbase + (q << 6) + gd] * 0.125f;
            float b = qi[qbase + (q << 6) + gd] * 0.125f;
            Qa[d * SQ + q] = make_float2(a, a);
            Qc[d * SQ + q] = make_float2(b, b);
        }
        // K fill: 32d x 32p, lane = d
        #pragma unroll
        for (int it = 0; it < 4; ++it) {
            int idx = tid + (it << 8);
            int d = idx & 31, p = idx >> 5, gd = hd + d;
            Kr2[d * SK + p] = make_float2(kr[kbase + (p << 6) + gd],
                                          kr[kbase + ((p + 32) << 6) + gd]);
            Ki2[d * SK + p] = make_float2(ki[kbase + (p << 6) + gd],
                                          ki[kbase + ((p + 32) << 6) + gd]);
        }
        __syncthreads();

        #pragma unroll 4
        for (int d = 0; d < 32; ++d) {
            F4U qa01, qa23, qc01, qc23;
            qa01.f = *reinterpret_cast<const float4*>(Qa + d * SQ + (ty << 2));
            qa23.f = *reinterpret_cast<const float4*>(Qa + d * SQ + (ty << 2) + 2);
            qc01.f = *reinterpret_cast<const float4*>(Qc + d * SQ + (ty << 2));
            qc23.f = *reinterpret_cast<const float4*>(Qc + d * SQ + (ty << 2) + 2);
            u64 kr0 = *reinterpret_cast<const u64*>(Kr2 + d * SK + tx);
            u64 kr1 = *reinterpret_cast<const u64*>(Kr2 + d * SK + tx + 16);
            u64 ki0 = *reinterpret_cast<const u64*>(Ki2 + d * SK + tx);
            u64 ki1 = *reinterpret_cast<const u64*>(Ki2 + d * SK + tx + 16);
            u64 kn0 = mul2(ki0, NEG1);
            u64 kn1 = mul2(ki1, NEG1);
            u64 qa[4] = { qa01.u[0], qa01.u[1], qa23.u[0], qa23.u[1] };
            u64 qc[4] = { qc01.u[0], qc01.u[1], qc23.u[0], qc23.u[1] };
            #pragma unroll
            for (int i = 0; i < 4; i++) {
                fma2(accr[i][0], qa[i], kr0);
                fma2(accr[i][0], qc[i], kn0);
                fma2(acci[i][0], qa[i], ki0);
                fma2(acci[i][0], qc[i], kr0);
                fma2(accr[i][1], qa[i], kr1);
                fma2(accr[i][1], qc[i], kn1);
                fma2(acci[i][1], qa[i], ki1);
                fma2(acci[i][1], qc[i], kr1);
            }
        }
        __syncthreads();
    }

    // Epilogue: store attn, mag^2 min/max partials (k = tx+16s and +32).
    float mn_[4], mx_[4];
    #pragma unroll
    for (int i = 0; i < 4; i++) {
        int qrow = (qt << 6) + (ty << 2) + i;
        size_t base = ((size_t)(bh << 10) + qrow) << 10;
        float mnv = 3.4e38f, mxv = 0.0f;
        #pragma unroll
        for (int s = 0; s < 2; s++) {
            float2 cr = upk(accr[i][s]);
            float2 ci = upk(acci[i][s]);
            int k0 = (kt << 6) + tx + (s << 4);
            g_ar[base + k0] = cr.x;      g_ai[base + k0] = ci.x;
            g_ar[base + k0 + 32] = cr.y; g_ai[base + k0 + 32] = ci.y;
            float m0 = cr.x * cr.x + ci.x * ci.x;
            float m1 = cr.y * cr.y + ci.y * ci.y;
            mnv = fminf(mnv, fminf(m0, m1));
            mxv = fmaxf(mxv, fmaxf(m0, m1));
        }
        mn_[i] = mnv; mx_[i] = mxv;
    }
    #pragma unroll
    for (int off = 8; off >= 1; off >>= 1) {
        #pragma unroll
        for (int i = 0; i < 4; i++) {
            mn_[i] = fminf(mn_[i], __shfl_xor_sync(0xffffffffu, mn_[i], off));
            mx_[i] = fmaxf(mx_[i], __shfl_xor_sync(0xffffffffu, mx_[i], off));
        }
    }
    if (tx == 0) {
        #pragma unroll
        for (int i = 0; i < 4; i++) {
            int qrow = (qt << 6) + (ty << 2) + i;
            g_pmin[((bh << 10) + qrow) * NKT + kt] = mn_[i];
            g_pmax[((bh << 10) + qrow) * NKT + kt] = mx_[i];
        }
    }
}

// ---------------------------------------------------------------------------
// K2: reduce partials -> mn = sqrt(min m2), inv = 1/(mx-mn).
// ---------------------------------------------------------------------------
__global__ void minmax_kernel()
{
    int r = blockIdx.x * 256 + threadIdx.x;
    float mn2 = g_pmin[r * NKT], mx2 = g_pmax[r * NKT];
    #pragma unroll
    for (int t = 1; t < NKT; t++) {
        mn2 = fminf(mn2, g_pmin[r * NKT + t]);
        mx2 = fmaxf(mx2, g_pmax[r * NKT + t]);
    }
    float mnv = sqrtf(mn2), mxv = sqrtf(mx2);
    g_mn[r] = mnv;
    g_inv[r] = 1.0f / (mxv - mnv);
}

// ---------------------------------------------------------------------------
// K3: out = normalize(attn) @ v (complex). 64q x 64d tile, k streamed in
// 32-chunks (32 chunks). d packed as (d, d+32) column pairs.
// ---------------------------------------------------------------------------
__global__ __launch_bounds__(256, 3) void av_kernel(
    const float* __restrict__ vr, const float* __restrict__ vi,
    float* __restrict__ out)
{
    extern __shared__ float2 sm3[];
    float2* Aa  = sm3;                // [32][SQ] (arn,arn)
    float2* Ac  = Aa  + 32 * SQ;      // [32][SQ] (ain,ain)
    float2* Vr2 = Ac  + 32 * SQ;      // [32][SK] (vr[d],vr[d+32])
    float2* Vi2 = Vr2 + 32 * SK;      // [32][SK]
    __shared__ float smn[64], sinv[64];

    const int qt = blockIdx.x, bh = blockIdx.y;
    const int tid = threadIdx.x;
    if (tid < 64) {
        int r = (bh << 10) + (qt << 6) + tid;
        smn[tid] = g_mn[r];
        sinv[tid] = g_inv[r];
    }
    __syncthreads();

    const int ty = tid >> 4, tx = tid & 15;
    const u64 NEG1 = pk(-1.0f, -1.0f);
    u64 accr[4][2], acci[4][2];
    #pragma unroll
    for (int i = 0; i < 4; i++) { accr[i][0]=0; accr[i][1]=0; acci[i][0]=0; acci[i][1]=0; }

    const size_t abase = ((size_t)(bh << 10) + (qt << 6)) << 10;

    for (int c = 0; c < 32; ++c) {
        // A fill: 32k x 64q, lane = k (coalesced); normalize on the fly.
        #pragma unroll
        for (int it = 0; it < 8; ++it) {
            int idx = tid + (it << 8);
            int kk = idx & 31, q = idx >> 5;
            size_t ao = abase + ((size_t)q << 10) + (c << 5) + kk;
            float ar = g_ar[ao], ai = g_ai[ao];
            float m2 = ar * ar + ai * ai;
            float rm = rsqrtf(m2);
            float f = (m2 * rm - smn[q]) * sinv[q] * rm;
            float arn = ar * f, ain = ai * f;
            Aa[kk * SQ + q] = make_float2(arn, arn);
            Ac[kk * SQ + q] = make_float2(ain, ain);
        }
        // V fill: 32k x 32dp, lane = dp (coalesced)
        #pragma unroll
        for (int it = 0; it < 4; ++it) {
            int idx = tid + (it << 8);
            int dp = idx & 31, kk = idx >> 5;
            int vo = (((bh << 10) + (c << 5) + kk) << 6) + dp;
            Vr2[kk * SK + dp] = make_float2(vr[vo], vr[vo + 32]);
            Vi2[kk * SK + dp] = make_float2(vi[vo], vi[vo + 32]);
        }
        __syncthreads();

        #pragma unroll 4
        for (int kk = 0; kk < 32; ++kk) {
            F4U aa01, aa23, ac01, ac23;
            aa01.f = *reinterpret_cast<const float4*>(Aa + kk * SQ + (ty << 2));
            aa23.f = *reinterpret_cast<const float4*>(Aa + kk * SQ + (ty << 2) + 2);
            ac01.f = *reinterpret_cast<const float4*>(Ac + kk * SQ + (ty << 2));
            ac23.f = *reinterpret_cast<const float4*>(Ac + kk * SQ + (ty << 2) + 2);
            u64 vr0 = *reinterpret_cast<const u64*>(Vr2 + kk * SK + tx);
            u64 vr1 = *reinterpret_cast<const u64*>(Vr2 + kk * SK + tx + 16);
            u64 vi0 = *reinterpret_cast<const u64*>(Vi2 + kk * SK + tx);
            u64 vi1 = *reinterpret_cast<const u64*>(Vi2 + kk * SK + tx + 16);
            u64 vn0 = mul2(vi0, NEG1);
            u64 vn1 = mul2(vi1, NEG1);
            u64 aa[4] = { aa01.u[0], aa01.u[1], aa23.u[0], aa23.u[1] };
            u64 ac[4] = { ac01.u[0], ac01.u[1], ac23.u[0], ac23.u[1] };
            #pragma unroll
            for (int i = 0; i < 4; i++) {
                fma2(accr[i][0], aa[i], vr0);
                fma2(accr[i][0], ac[i], vn0);
                fma2(acci[i][0], aa[i], vi0);
                fma2(acci[i][0], ac[i], vr0);
                fma2(accr[i][1], aa[i], vr1);
                fma2(accr[i][1], ac[i], vn1);
                fma2(acci[i][1], aa[i], vi1);
                fma2(acci[i][1], ac[i], vr1);
            }
        }
        __syncthreads();
    }

    // Output: [2][BH][S][D]; d = tx+16s and +32.
    #pragma unroll
    for (int i = 0; i < 4; i++) {
        int qrow = (qt << 6) + (ty << 2) + i;
        int ob = ((bh << 10) + qrow) << 6;
        #pragma unroll
        for (int s = 0; s < 2; s++) {
            int d0 = tx + (s << 4);
            float2 cr = upk(accr[i][s]);
            float2 ci = upk(acci[i][s]);
            out[ob + d0] = cr.x;
            out[ob + d0 + 32] = cr.y;
            out[ob + d0 + 4194304] = ci.x;
            out[ob + d0 + 32 + 4194304] = ci.y;
        }
    }
}

extern "C" void kernel_launch(void* const* d_in, const int* in_sizes, int n_in,
                              void* d_out, int out_size)
{
    (void)in_sizes; (void)n_in; (void)out_size;
    const float* qr = (const float*)d_in[0];
    const float* qi = (const float*)d_in[1];
    const float* kr = (const float*)d_in[2];
    const float* ki = (const float*)d_in[3];
    const float* vr = (const float*)d_in[4];
    const float* vi = (const float*)d_in[5];
    float* out = (float*)d_out;

    const int smem = (2 * 32 * SQ + 2 * 32 * SK) * (int)sizeof(float2);  // 51200
    cudaFuncSetAttribute(qk_kernel, cudaFuncAttributeMaxDynamicSharedMemorySize, smem);
    cudaFuncSetAttribute(av_kernel, cudaFuncAttributeMaxDynamicSharedMemorySize, smem);

    qk_kernel<<<dim3(16, 16, 64), 256, smem>>>(qr, qi, kr, ki);
    minmax_kernel<<<256, 256>>>();
    av_kernel<<<dim3(16, 64), 256, smem>>>(vr, vi, out);
}

// round 6
// speedup vs baseline: 2.4331x; 2.4315x over previous
#include <cuda_runtime.h>
#include <cuda_bf16.h>
#include <cstdint>

// Complex attention: tensor cores via mma.sync bf16 3-term split (portable PTX).
// B=8 H=8 S=1024 D=64.
// K1: attn=(q/8).k -> spill + per-(row,ktile) mag^2 min/max
// K2: row min/max reduce
// K3: normalize(attn) @ v

#define BHN 64
#define NKT 8

typedef unsigned long long u64;
typedef uint32_t u32;

__device__ float g_ar[(size_t)BHN * 1024 * 1024];   // 256 MB
__device__ float g_ai[(size_t)BHN * 1024 * 1024];   // 256 MB
__device__ float g_pmin[BHN * 1024 * NKT];
__device__ float g_pmax[BHN * 1024 * NKT];
__device__ float g_mn[BHN * 1024];
__device__ float g_inv[BHN * 1024];

__device__ __forceinline__ u32 smem_u32(const void* p) {
    u32 a;
    asm("{ .reg .u64 t; cvta.to.shared.u64 t, %1; cvt.u32.u64 %0, t; }"
        : "=r"(a) : "l"(p));
    return a;
}

#define SW128(x) ((x) ^ (((x) >> 3) & 0x70))

__device__ __forceinline__ void ldmx4(u32* r, u32 a) {
    asm volatile("ldmatrix.sync.aligned.m8n8.x4.shared.b16 {%0,%1,%2,%3}, [%4];"
        : "=r"(r[0]), "=r"(r[1]), "=r"(r[2]), "=r"(r[3]) : "r"(a));
}
__device__ __forceinline__ void ldmx2(u32* r, u32 a) {
    asm volatile("ldmatrix.sync.aligned.m8n8.x2.shared.b16 {%0,%1}, [%2];"
        : "=r"(r[0]), "=r"(r[1]) : "r"(a));
}
__device__ __forceinline__ void ldmx2t(u32* r, u32 a) {
    asm volatile("ldmatrix.sync.aligned.m8n8.x2.trans.shared.b16 {%0,%1}, [%2];"
        : "=r"(r[0]), "=r"(r[1]) : "r"(a));
}
__device__ __forceinline__ void mma16816(float* c, const u32* a, const u32* b) {
    asm volatile("mma.sync.aligned.m16n8k16.row.col.f32.bf16.bf16.f32 "
        "{%0,%1,%2,%3}, {%4,%5,%6,%7}, {%8,%9}, {%0,%1,%2,%3};"
        : "+f"(c[0]), "+f"(c[1]), "+f"(c[2]), "+f"(c[3])
        : "r"(a[0]), "r"(a[1]), "r"(a[2]), "r"(a[3]), "r"(b[0]), "r"(b[1]));
}

// fp32 pair -> bf16 hi pair + bf16 lo pair, one u32 store each, SW128 layout.
__device__ __forceinline__ void st_split2(char* hi, char* lo, int row, int cp, float2 v) {
    __nv_bfloat162 h = __float22bfloat162_rn(v);
    float2 hf = __bfloat1622float2(h);
    __nv_bfloat162 l = __float22bfloat162_rn(make_float2(v.x - hf.x, v.y - hf.y));
    u32 off = SW128((u32)(row * 128 + cp * 4));
    *(u32*)(hi + off) = *(u32*)&h;
    *(u32*)(lo + off) = *(u32*)&l;
}

#define TB16 16384
#define NEGS 0x80008000u

// ---------------------------------------------------------------------------
// K1: QK. CTA tile 128q x 128k, 8 warps (4m x 2n), warp tile 32q x 64k.
// attn_r = qr.kr - qi.ki ; attn_i = qr.ki + qi.kr  (3-term bf16 splits)
// ---------------------------------------------------------------------------
__global__ __launch_bounds__(256, 1) void qk_kernel(
    const float* __restrict__ qr, const float* __restrict__ qi,
    const float* __restrict__ kr, const float* __restrict__ ki)
{
    extern __shared__ __align__(128) char sm[];
    char* s_qrh = sm;
    char* s_qrl = s_qrh + TB16;
    char* s_qih = s_qrl + TB16;
    char* s_qil = s_qih + TB16;
    char* s_krh = s_qil + TB16;
    char* s_krl = s_krh + TB16;
    char* s_kih = s_krl + TB16;
    char* s_kil = s_kih + TB16;
    __shared__ float sMin[128][2], sMax[128][2];

    const int tid = threadIdx.x, wid = tid >> 5, lane = tid & 31;
    const int kt = blockIdx.x, qt = blockIdx.y, bh = blockIdx.z;

    // ---- fill (coalesced float2 loads, conflict-free u32 packed stores) ----
    {
        const size_t qbase = ((size_t)((bh << 10) + (qt << 7))) << 6;
        const size_t kbase = ((size_t)((bh << 10) + (kt << 7))) << 6;
        const int cp = tid & 31, r0 = tid >> 5;
        #pragma unroll
        for (int it = 0; it < 16; ++it) {
            int row = r0 + (it << 3);
            float2 a = *(const float2*)(qr + qbase + (row << 6) + cp * 2);
            float2 b = *(const float2*)(qi + qbase + (row << 6) + cp * 2);
            a.x *= 0.125f; a.y *= 0.125f;
            b.x *= 0.125f; b.y *= 0.125f;
            st_split2(s_qrh, s_qrl, row, cp, a);
            st_split2(s_qih, s_qil, row, cp, b);
            float2 c = *(const float2*)(kr + kbase + (row << 6) + cp * 2);
            float2 d = *(const float2*)(ki + kbase + (row << 6) + cp * 2);
            st_split2(s_krh, s_krl, row, cp, c);
            st_split2(s_kih, s_kil, row, cp, d);
        }
    }
    __syncthreads();

    // ---- compute ----
    const int wm = wid >> 1, wn = wid & 1;
    const int g = lane >> 2, tg = lane & 3;
    float accR[2][8][4] = {}, accI[2][8][4] = {};

    const u32 uqrh = smem_u32(s_qrh), uqrl = smem_u32(s_qrl);
    const u32 uqih = smem_u32(s_qih), uqil = smem_u32(s_qil);
    const u32 ukrh = smem_u32(s_krh), ukrl = smem_u32(s_krl);
    const u32 ukih = smem_u32(s_kih), ukil = smem_u32(s_kil);

    const u32 a_row = (u32)(wm * 32 + (lane & 15));
    const u32 a_cb  = (u32)((lane >> 4) * 16);
    const u32 b_row = (u32)(wn * 64 + (lane & 7));
    const u32 b_cb  = (u32)(((lane >> 3) & 1) * 16);

    for (int kb = 0; kb < 4; ++kb) {
        u32 Aqrh[2][4], Aqrl[2][4], Aqih[2][4], Aqil[2][4];
        #pragma unroll
        for (int mb = 0; mb < 2; ++mb) {
            u32 off = SW128((a_row + mb * 16) * 128 + kb * 32 + a_cb);
            ldmx4(Aqrh[mb], uqrh + off);
            ldmx4(Aqrl[mb], uqrl + off);
            ldmx4(Aqih[mb], uqih + off);
            ldmx4(Aqil[mb], uqil + off);
        }
        #pragma unroll
        for (int nb = 0; nb < 8; ++nb) {
            u32 off = SW128((b_row + nb * 8) * 128 + kb * 32 + b_cb);
            u32 Bkrh[2], Bkrl[2], Bkih[2], Bkil[2];
            ldmx2(Bkrh, ukrh + off);
            ldmx2(Bkrl, ukrl + off);
            ldmx2(Bkih, ukih + off);
            ldmx2(Bkil, ukil + off);
            u32 Bknh[2] = { Bkih[0] ^ NEGS, Bkih[1] ^ NEGS };
            u32 Bknl[2] = { Bkil[0] ^ NEGS, Bkil[1] ^ NEGS };
            #pragma unroll
            for (int mb = 0; mb < 2; ++mb) {
                mma16816(accR[mb][nb], Aqrh[mb], Bkrh);
                mma16816(accR[mb][nb], Aqrh[mb], Bkrl);
                mma16816(accR[mb][nb], Aqrl[mb], Bkrh);
                mma16816(accR[mb][nb], Aqih[mb], Bknh);
                mma16816(accR[mb][nb], Aqih[mb], Bknl);
                mma16816(accR[mb][nb], Aqil[mb], Bknh);
                mma16816(accI[mb][nb], Aqrh[mb], Bkih);
                mma16816(accI[mb][nb], Aqrh[mb], Bkil);
                mma16816(accI[mb][nb], Aqrl[mb], Bkih);
                mma16816(accI[mb][nb], Aqih[mb], Bkrh);
                mma16816(accI[mb][nb], Aqih[mb], Bkrl);
                mma16816(accI[mb][nb], Aqil[mb], Bkrh);
            }
        }
    }

    // ---- epilogue: store attn + row mag^2 min/max ----
    #pragma unroll
    for (int mb = 0; mb < 2; ++mb)
        #pragma unroll
        for (int half = 0; half < 2; ++half) {
            int rl = wm * 32 + mb * 16 + half * 8 + g;
            size_t ab = (((size_t)((bh << 10) + (qt << 7) + rl)) << 10)
                      + (kt << 7) + wn * 64 + tg * 2;
            float mn = 3.4e38f, mx = 0.0f;
            #pragma unroll
            for (int nb = 0; nb < 8; ++nb) {
                float x0 = accR[mb][nb][half * 2], x1 = accR[mb][nb][half * 2 + 1];
                float y0 = accI[mb][nb][half * 2], y1 = accI[mb][nb][half * 2 + 1];
                *(float2*)(g_ar + ab + nb * 8) = make_float2(x0, x1);
                *(float2*)(g_ai + ab + nb * 8) = make_float2(y0, y1);
                float m0 = x0 * x0 + y0 * y0, m1 = x1 * x1 + y1 * y1;
                mn = fminf(mn, fminf(m0, m1));
                mx = fmaxf(mx, fmaxf(m0, m1));
            }
            mn = fminf(mn, __shfl_xor_sync(0xffffffffu, mn, 1));
            mn = fminf(mn, __shfl_xor_sync(0xffffffffu, mn, 2));
            mx = fmaxf(mx, __shfl_xor_sync(0xffffffffu, mx, 1));
            mx = fmaxf(mx, __shfl_xor_sync(0xffffffffu, mx, 2));
            if (tg == 0) { sMin[rl][wn] = mn; sMax[rl][wn] = mx; }
        }
    __syncthreads();
    if (tid < 128) {
        float mn = fminf(sMin[tid][0], sMin[tid][1]);
        float mx = fmaxf(sMax[tid][0], sMax[tid][1]);
        int row = (qt << 7) + tid;
        g_pmin[((bh << 10) + row) * NKT + kt] = mn;
        g_pmax[((bh << 10) + row) * NKT + kt] = mx;
    }
}

// ---------------------------------------------------------------------------
// K2: reduce 8 partials/row -> mn = sqrt(min m2), inv = 1/(mx - mn).
// ---------------------------------------------------------------------------
__global__ void minmax_kernel()
{
    int r = blockIdx.x * 256 + threadIdx.x;   // 65536 rows
    float mn2 = g_pmin[r * NKT], mx2 = g_pmax[r * NKT];
    #pragma unroll
    for (int t = 1; t < NKT; t++) {
        mn2 = fminf(mn2, g_pmin[r * NKT + t]);
        mx2 = fmaxf(mx2, g_pmax[r * NKT + t]);
    }
    float mnv = sqrtf(mn2), mxv = sqrtf(mx2);
    g_mn[r] = mnv;
    g_inv[r] = 1.0f / (mxv - mnv);
}

// ---------------------------------------------------------------------------
// K3: AV. CTA tile 128q x 64d per (qt,bh); 16 k-chunks of 64.
// 8 warps (4m x 2n), warp tile 32q x 32d.
// out_r = ar.vr - ai.vi ; out_i = ar.vi + ai.vr
// V kept natural [k][d]; B frags via ldmatrix.x2.trans.
// ---------------------------------------------------------------------------
__global__ __launch_bounds__(256, 2) void av_kernel(
    const float* __restrict__ vr, const float* __restrict__ vi,
    float* __restrict__ out)
{
    extern __shared__ __align__(128) char sm[];
    char* s_arh = sm;                 // 16 KB each (128 x 128B)
    char* s_arl = s_arh + TB16;
    char* s_aih = s_arl + TB16;
    char* s_ail = s_aih + TB16;
    char* s_vrh = s_ail + TB16;       // 8 KB each (64 x 128B)
    char* s_vrl = s_vrh + 8192;
    char* s_vih = s_vrl + 8192;
    char* s_vil = s_vih + 8192;
    __shared__ float smn[128], sinv[128];

    const int tid = threadIdx.x, wid = tid >> 5, lane = tid & 31;
    const int qt = blockIdx.x, bh = blockIdx.y;

    if (tid < 128) {
        int r = (bh << 10) + (qt << 7) + tid;
        smn[tid] = g_mn[r];
        sinv[tid] = g_inv[r];
    }
    __syncthreads();

    const int wm = wid >> 1, wn = wid & 1;
    const int g = lane >> 2, tg = lane & 3;
    float accR[2][4][4] = {}, accI[2][4][4] = {};

    const u32 uarh = smem_u32(s_arh), uarl = smem_u32(s_arl);
    const u32 uaih = smem_u32(s_aih), uail = smem_u32(s_ail);
    const u32 uvrh = smem_u32(s_vrh), uvrl = smem_u32(s_vrl);
    const u32 uvih = smem_u32(s_vih), uvil = smem_u32(s_vil);

    const u32 a_row = (u32)(wm * 32 + (lane & 15));
    const u32 a_cb  = (u32)((lane >> 4) * 16);
    const u32 bt_row = (u32)(lane & 15);             // + kb*16
    const u32 bt_cb  = (u32)(wn * 64);               // + nb*16

    const size_t abase = ((size_t)((bh << 10) + (qt << 7))) << 10;
    const int cp = tid & 31, r0 = tid >> 5;

    for (int c = 0; c < 16; ++c) {
        // A fill: normalized attn [128q][64k]
        #pragma unroll
        for (int it = 0; it < 16; ++it) {
            int row = r0 + (it << 3);
            size_t ao = abase + ((size_t)row << 10) + (c << 6) + cp * 2;
            float2 a = *(const float2*)(g_ar + ao);
            float2 b = *(const float2*)(g_ai + ao);
            float mnv = smn[row], invv = sinv[row];
            float m20 = a.x * a.x + b.x * b.x;
            float m21 = a.y * a.y + b.y * b.y;
            float rm0 = rsqrtf(m20), rm1 = rsqrtf(m21);
            float f0 = (m20 * rm0 - mnv) * invv * rm0;
            float f1 = (m21 * rm1 - mnv) * invv * rm1;
            st_split2(s_arh, s_arl, row, cp, make_float2(a.x * f0, a.y * f1));
            st_split2(s_aih, s_ail, row, cp, make_float2(b.x * f0, b.y * f1));
        }
        // B fill: V natural [64k][64d]
        #pragma unroll
        for (int it = 0; it < 8; ++it) {
            int krow = r0 + (it << 3);
            size_t vo = ((size_t)((bh << 10) + (c << 6) + krow) << 6) + cp * 2;
            float2 x = *(const float2*)(vr + vo);
            float2 y = *(const float2*)(vi + vo);
            st_split2(s_vrh, s_vrl, krow, cp, x);
            st_split2(s_vih, s_vil, krow, cp, y);
        }
        __syncthreads();

        for (int kb = 0; kb < 4; ++kb) {
            u32 Aarh[2][4], Aarl[2][4], Aaih[2][4], Aail[2][4];
            #pragma unroll
            for (int mb = 0; mb < 2; ++mb) {
                u32 off = SW128((a_row + mb * 16) * 128 + kb * 32 + a_cb);
                ldmx4(Aarh[mb], uarh + off);
                ldmx4(Aarl[mb], uarl + off);
                ldmx4(Aaih[mb], uaih + off);
                ldmx4(Aail[mb], uail + off);
            }
            #pragma unroll
            for (int nb = 0; nb < 4; ++nb) {
                u32 off = SW128((bt_row + kb * 16) * 128 + bt_cb + nb * 16);
                u32 Bvrh[2], Bvrl[2], Bvih[2], Bvil[2];
                ldmx2t(Bvrh, uvrh + off);
                ldmx2t(Bvrl, uvrl + off);
                ldmx2t(Bvih, uvih + off);
                ldmx2t(Bvil, uvil + off);
                u32 Bvnh[2] = { Bvih[0] ^ NEGS, Bvih[1] ^ NEGS };
                u32 Bvnl[2] = { Bvil[0] ^ NEGS, Bvil[1] ^ NEGS };
                #pragma unroll
                for (int mb = 0; mb < 2; ++mb) {
                    mma16816(accR[mb][nb], Aarh[mb], Bvrh);
                    mma16816(accR[mb][nb], Aarh[mb], Bvrl);
                    mma16816(accR[mb][nb], Aarl[mb], Bvrh);
                    mma16816(accR[mb][nb], Aaih[mb], Bvnh);
                    mma16816(accR[mb][nb], Aaih[mb], Bvnl);
                    mma16816(accR[mb][nb], Aail[mb], Bvnh);
                    mma16816(accI[mb][nb], Aarh[mb], Bvih);
                    mma16816(accI[mb][nb], Aarh[mb], Bvil);
                    mma16816(accI[mb][nb], Aarl[mb], Bvih);
                    mma16816(accI[mb][nb], Aaih[mb], Bvrh);
                    mma16816(accI[mb][nb], Aaih[mb], Bvrl);
                    mma16816(accI[mb][nb], Aail[mb], Bvrh);
                }
            }
        }
        __syncthreads();
    }

    // ---- epilogue: out[2][64][1024][64], imag at +4194304 ----
    #pragma unroll
    for (int mb = 0; mb < 2; ++mb)
        #pragma unroll
        for (int half = 0; half < 2; ++half) {
            int row = (qt << 7) + wm * 32 + mb * 16 + half * 8 + g;
            int d = wn * 32 + tg * 2;
            size_t ob = ((size_t)((bh << 10) + row) << 6) + d;
            #pragma unroll
            for (int nb = 0; nb < 4; ++nb) {
                float2 cr = make_float2(accR[mb][nb][half * 2], accR[mb][nb][half * 2 + 1]);
                float2 ci = make_float2(accI[mb][nb][half * 2], accI[mb][nb][half * 2 + 1]);
                *(float2*)(out + ob + nb * 8) = cr;
                *(float2*)(out + ob + nb * 8 + 4194304) = ci;
            }
        }
}

extern "C" void kernel_launch(void* const* d_in, const int* in_sizes, int n_in,
                              void* d_out, int out_size)
{
    (void)in_sizes; (void)n_in; (void)out_size;
    const float* qr = (const float*)d_in[0];
    const float* qi = (const float*)d_in[1];
    const float* kr = (const float*)d_in[2];
    const float* ki = (const float*)d_in[3];
    const float* vr = (const float*)d_in[4];
    const float* vi = (const float*)d_in[5];
    float* out = (float*)d_out;

    const int smem_qk = 8 * TB16;             // 131072
    const int smem_av = 4 * TB16 + 4 * 8192;  // 98304
    cudaFuncSetAttribute(qk_kernel, cudaFuncAttributeMaxDynamicSharedMemorySize, smem_qk);
    cudaFuncSetAttribute(av_kernel, cudaFuncAttributeMaxDynamicSharedMemorySize, smem_av);

    qk_kernel<<<dim3(8, 8, 64), 256, smem_qk>>>(qr, qi, kr, ki);
    minmax_kernel<<<256, 256>>>();
    av_kernel<<<dim3(8, 64), 256, smem_av>>>(vr, vi, out);
}

// round 8
// speedup vs baseline: 2.6149x; 1.0747x over previous
#include <cuda_runtime.h>
#include <cuda_bf16.h>
#include <cstdint>

// Complex attention: tensor cores via mma.sync bf16 3-term split (portable PTX).
// B=8 H=8 S=1024 D=64.
// R7: QK retiled to 128q x 64k, 96KB smem, <=128 regs -> 2 CTAs/SM.

#define BHN 64
#define NKT 16

typedef unsigned long long u64;
typedef uint32_t u32;

__device__ float g_ar[(size_t)BHN * 1024 * 1024];   // 256 MB
__device__ float g_ai[(size_t)BHN * 1024 * 1024];   // 256 MB
__device__ float g_pmin[BHN * 1024 * NKT];
__device__ float g_pmax[BHN * 1024 * NKT];
__device__ float g_mn[BHN * 1024];
__device__ float g_inv[BHN * 1024];

__device__ __forceinline__ u32 smem_u32(const void* p) {
    u32 a;
    asm("{ .reg .u64 t; cvta.to.shared.u64 t, %1; cvt.u32.u64 %0, t; }"
        : "=r"(a) : "l"(p));
    return a;
}

#define SW128(x) ((x) ^ (((x) >> 3) & 0x70))

__device__ __forceinline__ void ldmx4(u32* r, u32 a) {
    asm volatile("ldmatrix.sync.aligned.m8n8.x4.shared.b16 {%0,%1,%2,%3}, [%4];"
        : "=r"(r[0]), "=r"(r[1]), "=r"(r[2]), "=r"(r[3]) : "r"(a));
}
__device__ __forceinline__ void ldmx2(u32* r, u32 a) {
    asm volatile("ldmatrix.sync.aligned.m8n8.x2.shared.b16 {%0,%1}, [%2];"
        : "=r"(r[0]), "=r"(r[1]) : "r"(a));
}
__device__ __forceinline__ void ldmx2t(u32* r, u32 a) {
    asm volatile("ldmatrix.sync.aligned.m8n8.x2.trans.shared.b16 {%0,%1}, [%2];"
        : "=r"(r[0]), "=r"(r[1]) : "r"(a));
}
__device__ __forceinline__ void mma16816(float* c, const u32* a, const u32* b) {
    asm volatile("mma.sync.aligned.m16n8k16.row.col.f32.bf16.bf16.f32 "
        "{%0,%1,%2,%3}, {%4,%5,%6,%7}, {%8,%9}, {%0,%1,%2,%3};"
        : "+f"(c[0]), "+f"(c[1]), "+f"(c[2]), "+f"(c[3])
        : "r"(a[0]), "r"(a[1]), "r"(a[2]), "r"(a[3]), "r"(b[0]), "r"(b[1]));
}

// fp32 pair -> bf16 hi pair + bf16 lo pair, one u32 store each, SW128 layout.
__device__ __forceinline__ void st_split2(char* hi, char* lo, int row, int cp, float2 v) {
    __nv_bfloat162 h = __float22bfloat162_rn(v);
    float2 hf = __bfloat1622float2(h);
    __nv_bfloat162 l = __float22bfloat162_rn(make_float2(v.x - hf.x, v.y - hf.y));
    u32 off = SW128((u32)(row * 128 + cp * 4));
    *(u32*)(hi + off) = *(u32*)&h;
    *(u32*)(lo + off) = *(u32*)&l;
}

#define TB16 16384
#define TB8  8192
#define NEGS 0x80008000u

// ---------------------------------------------------------------------------
// K1: QK. CTA tile 128q x 64k, 8 warps (4m x 2n), warp tile 32q x 32k.
// attn_r = qr.kr - qi.ki ; attn_i = qr.ki + qi.kr  (3-term bf16 splits)
// smem 96KB, regs capped at 128 -> 2 CTAs/SM.
// ---------------------------------------------------------------------------
__global__ __launch_bounds__(256, 2) void qk_kernel(
    const float* __restrict__ qr, const float* __restrict__ qi,
    const float* __restrict__ kr, const float* __restrict__ ki)
{
    extern __shared__ __align__(128) char sm[];
    char* s_qrh = sm;                 // 16 KB each (128 x 128B)
    char* s_qrl = s_qrh + TB16;
    char* s_qih = s_qrl + TB16;
    char* s_qil = s_qih + TB16;
    char* s_krh = s_qil + TB16;       // 8 KB each (64 x 128B)
    char* s_krl = s_krh + TB8;
    char* s_kih = s_krl + TB8;
    char* s_kil = s_kih + TB8;
    __shared__ float sMin[128][2], sMax[128][2];

    const int tid = threadIdx.x, wid = tid >> 5, lane = tid & 31;
    const int kt = blockIdx.x, qt = blockIdx.y, bh = blockIdx.z;

    // ---- fill ----
    {
        const size_t qbase = ((size_t)((bh << 10) + (qt << 7))) << 6;
        const size_t kbase = ((size_t)((bh << 10) + (kt << 6))) << 6;
        const int cp = tid & 31, r0 = tid >> 5;
        #pragma unroll
        for (int it = 0; it < 16; ++it) {
            int row = r0 + (it << 3);
            float2 a = *(const float2*)(qr + qbase + (row << 6) + cp * 2);
            float2 b = *(const float2*)(qi + qbase + (row << 6) + cp * 2);
            a.x *= 0.125f; a.y *= 0.125f;
            b.x *= 0.125f; b.y *= 0.125f;
            st_split2(s_qrh, s_qrl, row, cp, a);
            st_split2(s_qih, s_qil, row, cp, b);
        }
        #pragma unroll
        for (int it = 0; it < 8; ++it) {
            int row = r0 + (it << 3);
            float2 c = *(const float2*)(kr + kbase + (row << 6) + cp * 2);
            float2 d = *(const float2*)(ki + kbase + (row << 6) + cp * 2);
            st_split2(s_krh, s_krl, row, cp, c);
            st_split2(s_kih, s_kil, row, cp, d);
        }
    }
    __syncthreads();

    // ---- compute ----
    const int wm = wid >> 1, wn = wid & 1;
    const int g = lane >> 2, tg = lane & 3;
    float accR[2][4][4] = {}, accI[2][4][4] = {};

    const u32 uqrh = smem_u32(s_qrh), uqrl = smem_u32(s_qrl);
    const u32 uqih = smem_u32(s_qih), uqil = smem_u32(s_qil);
    const u32 ukrh = smem_u32(s_krh), ukrl = smem_u32(s_krl);
    const u32 ukih = smem_u32(s_kih), ukil = smem_u32(s_kil);

    const u32 a_row = (u32)(wm * 32 + (lane & 15));
    const u32 a_cb  = (u32)((lane >> 4) * 16);
    const u32 b_row = (u32)(wn * 32 + (lane & 7));
    const u32 b_cb  = (u32)(((lane >> 3) & 1) * 16);

    #pragma unroll
    for (int kb = 0; kb < 4; ++kb) {
        u32 Aqrh[2][4], Aqrl[2][4], Aqih[2][4], Aqil[2][4];
        #pragma unroll
        for (int mb = 0; mb < 2; ++mb) {
            u32 off = SW128((a_row + mb * 16) * 128 + kb * 32 + a_cb);
            ldmx4(Aqrh[mb], uqrh + off);
            ldmx4(Aqrl[mb], uqrl + off);
            ldmx4(Aqih[mb], uqih + off);
            ldmx4(Aqil[mb], uqil + off);
        }
        #pragma unroll
        for (int nb = 0; nb < 4; ++nb) {
            u32 off = SW128((b_row + nb * 8) * 128 + kb * 32 + b_cb);
            u32 Bkrh[2], Bkrl[2], Bkih[2], Bkil[2];
            ldmx2(Bkrh, ukrh + off);
            ldmx2(Bkrl, ukrl + off);
            ldmx2(Bkih, ukih + off);
            ldmx2(Bkil, ukil + off);
            u32 Bknh[2] = { Bkih[0] ^ NEGS, Bkih[1] ^ NEGS };
            u32 Bknl[2] = { Bkil[0] ^ NEGS, Bkil[1] ^ NEGS };
            #pragma unroll
            for (int mb = 0; mb < 2; ++mb) {
                mma16816(accR[mb][nb], Aqrh[mb], Bkrh);
                mma16816(accR[mb][nb], Aqrh[mb], Bkrl);
                mma16816(accR[mb][nb], Aqrl[mb], Bkrh);
                mma16816(accR[mb][nb], Aqih[mb], Bknh);
                mma16816(accR[mb][nb], Aqih[mb], Bknl);
                mma16816(accR[mb][nb], Aqil[mb], Bknh);
                mma16816(accI[mb][nb], Aqrh[mb], Bkih);
                mma16816(accI[mb][nb], Aqrh[mb], Bkil);
                mma16816(accI[mb][nb], Aqrl[mb], Bkih);
                mma16816(accI[mb][nb], Aqih[mb], Bkrh);
                mma16816(accI[mb][nb], Aqih[mb], Bkrl);
                mma16816(accI[mb][nb], Aqil[mb], Bkrh);
            }
        }
    }

    // ---- epilogue: store attn + row mag^2 min/max ----
    #pragma unroll
    for (int mb = 0; mb < 2; ++mb)
        #pragma unroll
        for (int half = 0; half < 2; ++half) {
            int rl = wm * 32 + mb * 16 + half * 8 + g;
            size_t ab = (((size_t)((bh << 10) + (qt << 7) + rl)) << 10)
                      + (kt << 6) + wn * 32 + tg * 2;
            float mn = 3.4e38f, mx = 0.0f;
            #pragma unroll
            for (int nb = 0; nb < 4; ++nb) {
                float x0 = accR[mb][nb][half * 2], x1 = accR[mb][nb][half * 2 + 1];
                float y0 = accI[mb][nb][half * 2], y1 = accI[mb][nb][half * 2 + 1];
                *(float2*)(g_ar + ab + nb * 8) = make_float2(x0, x1);
                *(float2*)(g_ai + ab + nb * 8) = make_float2(y0, y1);
                float m0 = x0 * x0 + y0 * y0, m1 = x1 * x1 + y1 * y1;
                mn = fminf(mn, fminf(m0, m1));
                mx = fmaxf(mx, fmaxf(m0, m1));
            }
            mn = fminf(mn, __shfl_xor_sync(0xffffffffu, mn, 1));
            mn = fminf(mn, __shfl_xor_sync(0xffffffffu, mn, 2));
            mx = fmaxf(mx, __shfl_xor_sync(0xffffffffu, mx, 1));
            mx = fmaxf(mx, __shfl_xor_sync(0xffffffffu, mx, 2));
            if (tg == 0) { sMin[rl][wn] = mn; sMax[rl][wn] = mx; }
        }
    __syncthreads();
    if (tid < 128) {
        float mn = fminf(sMin[tid][0], sMin[tid][1]);
        float mx = fmaxf(sMax[tid][0], sMax[tid][1]);
        int row = (qt << 7) + tid;
        g_pmin[((bh << 10) + row) * NKT + kt] = mn;
        g_pmax[((bh << 10) + row) * NKT + kt] = mx;
    }
}

// ---------------------------------------------------------------------------
// K2: reduce 16 partials/row -> mn = sqrt(min m2), inv = 1/(mx - mn).
// ---------------------------------------------------------------------------
__global__ void minmax_kernel()
{
    int r = blockIdx.x * 256 + threadIdx.x;   // 65536 rows
    float mn2 = g_pmin[r * NKT], mx2 = g_pmax[r * NKT];
    #pragma unroll
    for (int t = 1; t < NKT; t++) {
        mn2 = fminf(mn2, g_pmin[r * NKT + t]);
        mx2 = fmaxf(mx2, g_pmax[r * NKT + t]);
    }
    float mnv = sqrtf(mn2), mxv = sqrtf(mx2);
    g_mn[r] = mnv;
    g_inv[r] = 1.0f / (mxv - mnv);
}

// ---------------------------------------------------------------------------
// K3: AV. CTA tile 128q x 64d per (qt,bh); 16 k-chunks of 64.
// 8 warps (4m x 2n), warp tile 32q x 32d.
// out_r = ar.vr - ai.vi ; out_i = ar.vi + ai.vr
// V kept natural [k][d]; B frags via ldmatrix.x2.trans.
// ---------------------------------------------------------------------------
__global__ __launch_bounds__(256, 2) void av_kernel(
    const float* __restrict__ vr, const float* __restrict__ vi,
    float* __restrict__ out)
{
    extern __shared__ __align__(128) char sm[];
    char* s_arh = sm;                 // 16 KB each (128 x 128B)
    char* s_arl = s_arh + TB16;
    char* s_aih = s_arl + TB16;
    char* s_ail = s_aih + TB16;
    char* s_vrh = s_ail + TB16;       // 8 KB each (64 x 128B)
    char* s_vrl = s_vrh + TB8;
    char* s_vih = s_vrl + TB8;
    char* s_vil = s_vih + TB8;
    __shared__ float smn[128], sinv[128];

    const int tid = threadIdx.x, wid = tid >> 5, lane = tid & 31;
    const int qt = blockIdx.x, bh = blockIdx.y;

    if (tid < 128) {
        int r = (bh << 10) + (qt << 7) + tid;
        smn[tid] = g_mn[r];
        sinv[tid] = g_inv[r];
    }
    __syncthreads();

    const int wm = wid >> 1, wn = wid & 1;
    const int g = lane >> 2, tg = lane & 3;
    float accR[2][4][4] = {}, accI[2][4][4] = {};

    const u32 uarh = smem_u32(s_arh), uarl = smem_u32(s_arl);
    const u32 uaih = smem_u32(s_aih), uail = smem_u32(s_ail);
    const u32 uvrh = smem_u32(s_vrh), uvrl = smem_u32(s_vrl);
    const u32 uvih = smem_u32(s_vih), uvil = smem_u32(s_vil);

    const u32 a_row = (u32)(wm * 32 + (lane & 15));
    const u32 a_cb  = (u32)((lane >> 4) * 16);
    const u32 bt_row = (u32)(lane & 15);             // + kb*16
    const u32 bt_cb  = (u32)(wn * 64);               // + nb*16

    const size_t abase = ((size_t)((bh << 10) + (qt << 7))) << 10;
    const int cp = tid & 31, r0 = tid >> 5;

    for (int c = 0; c < 16; ++c) {
        // A fill: normalized attn [128q][64k]
        #pragma unroll
        for (int it = 0; it < 16; ++it) {
            int row = r0 + (it << 3);
            size_t ao = abase + ((size_t)row << 10) + (c << 6) + cp * 2;
            float2 a = *(const float2*)(g_ar + ao);
            float2 b = *(const float2*)(g_ai + ao);
            float mnv = smn[row], invv = sinv[row];
            float m20 = a.x * a.x + b.x * b.x;
            float m21 = a.y * a.y + b.y * b.y;
            float rm0 = rsqrtf(m20), rm1 = rsqrtf(m21);
            float f0 = (m20 * rm0 - mnv) * invv * rm0;
            float f1 = (m21 * rm1 - mnv) * invv * rm1;
            st_split2(s_arh, s_arl, row, cp, make_float2(a.x * f0, a.y * f1));
            st_split2(s_aih, s_ail, row, cp, make_float2(b.x * f0, b.y * f1));
        }
        // B fill: V natural [64k][64d]
        #pragma unroll
        for (int it = 0; it < 8; ++it) {
            int krow = r0 + (it << 3);
            size_t vo = ((size_t)((bh << 10) + (c << 6) + krow) << 6) + cp * 2;
            float2 x = *(const float2*)(vr + vo);
            float2 y = *(const float2*)(vi + vo);
            st_split2(s_vrh, s_vrl, krow, cp, x);
            st_split2(s_vih, s_vil, krow, cp, y);
        }
        __syncthreads();

        #pragma unroll
        for (int kb = 0; kb < 4; ++kb) {
            u32 Aarh[2][4], Aarl[2][4], Aaih[2][4], Aail[2][4];
            #pragma unroll
            for (int mb = 0; mb < 2; ++mb) {
                u32 off = SW128((a_row + mb * 16) * 128 + kb * 32 + a_cb);
                ldmx4(Aarh[mb], uarh + off);
                ldmx4(Aarl[mb], uarl + off);
                ldmx4(Aaih[mb], uaih + off);
                ldmx4(Aail[mb], uail + off);
            }
            #pragma unroll
            for (int nb = 0; nb < 4; ++nb) {
                u32 off = SW128((bt_row + kb * 16) * 128 + bt_cb + nb * 16);
                u32 Bvrh[2], Bvrl[2], Bvih[2], Bvil[2];
                ldmx2t(Bvrh, uvrh + off);
                ldmx2t(Bvrl, uvrl + off);
                ldmx2t(Bvih, uvih + off);
                ldmx2t(Bvil, uvil + off);
                u32 Bvnh[2] = { Bvih[0] ^ NEGS, Bvih[1] ^ NEGS };
                u32 Bvnl[2] = { Bvil[0] ^ NEGS, Bvil[1] ^ NEGS };
                #pragma unroll
                for (int mb = 0; mb < 2; ++mb) {
                    mma16816(accR[mb][nb], Aarh[mb], Bvrh);
                    mma16816(accR[mb][nb], Aarh[mb], Bvrl);
                    mma16816(accR[mb][nb], Aarl[mb], Bvrh);
                    mma16816(accR[mb][nb], Aaih[mb], Bvnh);
                    mma16816(accR[mb][nb], Aaih[mb], Bvnl);
                    mma16816(accR[mb][nb], Aail[mb], Bvnh);
                    mma16816(accI[mb][nb], Aarh[mb], Bvih);
                    mma16816(accI[mb][nb], Aarh[mb], Bvil);
                    mma16816(accI[mb][nb], Aarl[mb], Bvih);
                    mma16816(accI[mb][nb], Aaih[mb], Bvrh);
                    mma16816(accI[mb][nb], Aaih[mb], Bvrl);
                    mma16816(accI[mb][nb], Aail[mb], Bvrh);
                }
            }
        }
        __syncthreads();
    }

    // ---- epilogue: out[2][64][1024][64], imag at +4194304 ----
    #pragma unroll
    for (int mb = 0; mb < 2; ++mb)
        #pragma unroll
        for (int half = 0; half < 2; ++half) {
            int row = (qt << 7) + wm * 32 + mb * 16 + half * 8 + g;
            int d = wn * 32 + tg * 2;
            size_t ob = ((size_t)((bh << 10) + row) << 6) + d;
            #pragma unroll
            for (int nb = 0; nb < 4; ++nb) {
                float2 cr = make_float2(accR[mb][nb][half * 2], accR[mb][nb][half * 2 + 1]);
                float2 ci = make_float2(accI[mb][nb][half * 2], accI[mb][nb][half * 2 + 1]);
                *(float2*)(out + ob + nb * 8) = cr;
                *(float2*)(out + ob + nb * 8 + 4194304) = ci;
            }
        }
}

extern "C" void kernel_launch(void* const* d_in, const int* in_sizes, int n_in,
                              void* d_out, int out_size)
{
    (void)in_sizes; (void)n_in; (void)out_size;
    const float* qr = (const float*)d_in[0];
    const float* qi = (const float*)d_in[1];
    const float* kr = (const float*)d_in[2];
    const float* ki = (const float*)d_in[3];
    const float* vr = (const float*)d_in[4];
    const float* vi = (const float*)d_in[5];
    float* out = (float*)d_out;

    const int smem_qk = 4 * TB16 + 4 * TB8;   // 98304
    const int smem_av = 4 * TB16 + 4 * TB8;   // 98304
    cudaFuncSetAttribute(qk_kernel, cudaFuncAttributeMaxDynamicSharedMemorySize, smem_qk);
    cudaFuncSetAttribute(av_kernel, cudaFuncAttributeMaxDynamicSharedMemorySize, smem_av);

    qk_kernel<<<dim3(16, 8, 64), 256, smem_qk>>>(qr, qi, kr, ki);
    minmax_kernel<<<256, 256>>>();
    av_kernel<<<dim3(8, 64), 256, smem_av>>>(vr, vi, out);
}